// round 3
// baseline (speedup 1.0000x reference)
#include <cuda_runtime.h>
#include <cuda_bf16.h>
#include <cstdint>

#define NN 50000
#define NE 800000
#define EE (NE + NN)   // edges + self loops = 850000
#define HW 256
#define IN_FEAT 128
#define OUTF 40

// ---------------- scratch (static device globals; no runtime allocation) ----
__device__ float g_h[NN * HW];      // transformed features  (x @ W)
__device__ float g_feat[NN * HW];   // layer output / next layer input
__device__ float g_srcl[NN * 4];
__device__ float g_dstl[NN * 4];
__device__ float g_denom[NN * 4];
__device__ float g_coef[EE * 4];    // per-edge (sorted order) exp values
__device__ int   g_src2[EE];
__device__ int   g_dst2[EE];
__device__ int   g_src_sorted[EE];
__device__ int   g_counts[NN];
__device__ int   g_fill[NN];
__device__ int   g_rowptr[NN + 1];
__device__ int   g_is64;            // edge_index dtype flag

// ---------------- dtype detection: is edge_index int64 or int32? ----------
__global__ void k_detect(const void* __restrict__ ei) {
    if (threadIdx.x != 0 || blockIdx.x != 0) return;
    const long long* p64 = (const long long*)ei;
    bool ok64 = true;
    for (int i = 0; i < 512; i++) {
        long long v = p64[i];
        if (v < 0 || v >= (long long)NN) { ok64 = false; break; }
    }
    g_is64 = ok64 ? 1 : 0;
}

// ---------------- CSR build ----------------
__global__ void k_zero_counts(int* counts, int n) {
    int i = blockIdx.x * blockDim.x + threadIdx.x;
    if (i < n) counts[i] = 0;
}

__global__ void k_build_edges(const void* __restrict__ ei,
                              int* __restrict__ src2, int* __restrict__ dst2,
                              int* __restrict__ counts) {
    int e = blockIdx.x * blockDim.x + threadIdx.x;
    if (e >= EE) return;
    int s, d;
    if (e < NE) {
        if (g_is64) {
            const long long* p = (const long long*)ei;
            s = (int)p[e]; d = (int)p[NE + e];
        } else {
            const int* p = (const int*)ei;
            s = p[e]; d = p[NE + e];
        }
        // defensive clamp: out-of-range becomes wrong-answer, never a fault
        s = min(max(s, 0), NN - 1);
        d = min(max(d, 0), NN - 1);
    } else {
        s = d = e - NE;          // self loop
    }
    src2[e] = s;
    dst2[e] = d;
    atomicAdd(&counts[d], 1);
}

// single-block exclusive scan of counts[NN] -> rowptr, fill
__global__ void k_scan(const int* __restrict__ counts,
                       int* __restrict__ rowptr, int* __restrict__ fill) {
    __shared__ int ssum[1024];
    int tid = threadIdx.x;
    const int per = (NN + 1023) / 1024;
    int start = tid * per;
    int end = start + per; if (end > NN) end = NN;
    int s = 0;
    for (int i = start; i < end; i++) s += counts[i];
    ssum[tid] = s;
    __syncthreads();
    for (int off = 1; off < 1024; off <<= 1) {
        int v = 0;
        if (tid >= off) v = ssum[tid - off];
        __syncthreads();
        if (tid >= off) ssum[tid] += v;
        __syncthreads();
    }
    int run = (tid == 0) ? 0 : ssum[tid - 1];
    for (int i = start; i < end; i++) {
        rowptr[i] = run; fill[i] = run;
        run += counts[i];
    }
    if (tid == 1023) rowptr[NN] = ssum[1023];
}

__global__ void k_scatter(const int* __restrict__ src2, const int* __restrict__ dst2,
                          int* __restrict__ fill, int* __restrict__ src_sorted) {
    int e = blockIdx.x * blockDim.x + threadIdx.x;
    if (e >= EE) return;
    int d = dst2[e];
    int p = atomicAdd(&fill[d], 1);
    src_sorted[p] = src2[e];
}

// ---------------- SGEMM: C[M,N] = A[M,K] @ B[K,N] (+bias)(+relu) ----------------
#define BM 64
#define BN 64
#define BK 16
__global__ void k_sgemm(const float* __restrict__ A, const float* __restrict__ B,
                        float* __restrict__ C, int M, int N, int K,
                        const float* __restrict__ bias, int do_relu) {
    __shared__ float As[BK][BM + 4];
    __shared__ float Bs[BK][BN];
    int tid = threadIdx.x;          // 256 threads
    int tx = tid & 15, ty = tid >> 4;
    int row0 = blockIdx.y * BM, col0 = blockIdx.x * BN;
    float acc[4][4] = {};
    int am = tid >> 2, ak = (tid & 3) * 4;  // A tile loader: row am, 4 floats at ak
    int bk = tid >> 4, bn = (tid & 15) * 4; // B tile loader: row bk, 4 floats at bn

    for (int k0 = 0; k0 < K; k0 += BK) {
        float4 av = make_float4(0.f, 0.f, 0.f, 0.f);
        int ar = row0 + am;
        if (ar < M) av = *(const float4*)(A + (size_t)ar * K + k0 + ak);
        As[ak + 0][am] = av.x; As[ak + 1][am] = av.y;
        As[ak + 2][am] = av.z; As[ak + 3][am] = av.w;

        float4 bv = make_float4(0.f, 0.f, 0.f, 0.f);
        int bc = col0 + bn;
        if (bc < N) bv = *(const float4*)(B + (size_t)(k0 + bk) * N + bc);
        Bs[bk][bn + 0] = bv.x; Bs[bk][bn + 1] = bv.y;
        Bs[bk][bn + 2] = bv.z; Bs[bk][bn + 3] = bv.w;
        __syncthreads();

#pragma unroll
        for (int kk = 0; kk < BK; kk++) {
            float a[4], b[4];
#pragma unroll
            for (int i = 0; i < 4; i++) a[i] = As[kk][ty * 4 + i];
#pragma unroll
            for (int j = 0; j < 4; j++) b[j] = Bs[kk][tx * 4 + j];
#pragma unroll
            for (int i = 0; i < 4; i++)
#pragma unroll
                for (int j = 0; j < 4; j++) acc[i][j] += a[i] * b[j];
        }
        __syncthreads();
    }

#pragma unroll
    for (int i = 0; i < 4; i++) {
        int r = row0 + ty * 4 + i;
        if (r >= M) continue;
#pragma unroll
        for (int j = 0; j < 4; j++) {
            int c = col0 + tx * 4 + j;
            if (c >= N) continue;
            float v = acc[i][j];
            if (bias) v += bias[c];
            if (do_relu) v = fmaxf(v, 0.f);
            C[(size_t)r * N + c] = v;
        }
    }
}

// ---------------- per-node attention logits: warp per node ----------------
__global__ void k_logits(const float* __restrict__ h, const float* __restrict__ a_s,
                         const float* __restrict__ a_d,
                         float* __restrict__ srcl, float* __restrict__ dstl) {
    int warp = (blockIdx.x * blockDim.x + threadIdx.x) >> 5;
    int lane = threadIdx.x & 31;
    if (warp >= NN) return;
    int n = warp;
    const float4* hp = (const float4*)(h + (size_t)n * HW) + lane * 2;
    float4 v0 = hp[0], v1 = hp[1];
    int head = lane >> 3, sub = lane & 7;
    const float4* ap = (const float4*)(a_s + head * 64 + sub * 8);
    const float4* dp = (const float4*)(a_d + head * 64 + sub * 8);
    float4 s0 = ap[0], s1 = ap[1];
    float4 d0 = dp[0], d1 = dp[1];
    float ps = v0.x * s0.x + v0.y * s0.y + v0.z * s0.z + v0.w * s0.w
             + v1.x * s1.x + v1.y * s1.y + v1.z * s1.z + v1.w * s1.w;
    float pd = v0.x * d0.x + v0.y * d0.y + v0.z * d0.z + v0.w * d0.w
             + v1.x * d1.x + v1.y * d1.y + v1.z * d1.z + v1.w * d1.w;
#pragma unroll
    for (int off = 4; off >= 1; off >>= 1) {
        ps += __shfl_down_sync(0xffffffffu, ps, off, 8);
        pd += __shfl_down_sync(0xffffffffu, pd, off, 8);
    }
    if (sub == 0) {
        srcl[n * 4 + head] = ps;
        dstl[n * 4 + head] = pd;
    }
}

// ---------------- segment softmax: one thread per (node, head) ----------------
__global__ void k_attn(const float* __restrict__ srcl, const float* __restrict__ dstl,
                       const int* __restrict__ rowptr, const int* __restrict__ src_sorted,
                       float* __restrict__ coef, float* __restrict__ denom) {
    int t = blockIdx.x * blockDim.x + threadIdx.x;
    if (t >= NN * 4) return;
    int n = t >> 2, hd = t & 3;
    float dl = dstl[t];
    int b = rowptr[n], e = rowptr[n + 1];
    float mx = -1e30f;
    for (int i = b; i < e; i++) {
        int s = src_sorted[i];
        float a = srcl[s * 4 + hd] + dl;
        a = a > 0.f ? a : 0.2f * a;       // leaky_relu(0.2)
        coef[i * 4 + hd] = a;
        mx = fmaxf(mx, a);
    }
    float sum = 0.f;
    for (int i = b; i < e; i++) {
        float ev = __expf(coef[i * 4 + hd] - mx);
        coef[i * 4 + hd] = ev;
        sum += ev;
    }
    denom[t] = sum;
}

// ---------------- aggregation: warp per destination node, no atomics -------
__global__ void k_agg(const float* __restrict__ h, const int* __restrict__ rowptr,
                      const int* __restrict__ src_sorted, const float* __restrict__ coef,
                      const float* __restrict__ denom, const float* __restrict__ bias,
                      float* __restrict__ out) {
    int warp = (blockIdx.x * blockDim.x + threadIdx.x) >> 5;
    int lane = threadIdx.x & 31;
    if (warp >= NN) return;
    int n = warp;
    int head = lane >> 3;
    float rinv = 1.0f / denom[n * 4 + head];
    int b = rowptr[n], e = rowptr[n + 1];
    float4 a0 = make_float4(0.f, 0.f, 0.f, 0.f);
    float4 a1 = make_float4(0.f, 0.f, 0.f, 0.f);
    for (int i = b; i < e; i++) {
        int s = src_sorted[i];
        float4 cq = ((const float4*)coef)[i];
        float c = (head == 0) ? cq.x : (head == 1) ? cq.y : (head == 2) ? cq.z : cq.w;
        c *= rinv;
        const float4* hp = (const float4*)(h + (size_t)s * HW) + lane * 2;
        float4 v0 = hp[0], v1 = hp[1];
        a0.x += v0.x * c; a0.y += v0.y * c; a0.z += v0.z * c; a0.w += v0.w * c;
        a1.x += v1.x * c; a1.y += v1.y * c; a1.z += v1.z * c; a1.w += v1.w * c;
    }
    const float4* bp = (const float4*)bias + lane * 2;
    float4 b0 = bp[0], b1 = bp[1];
    float4 o0, o1;
    o0.x = fmaxf(a0.x + b0.x, 0.f); o0.y = fmaxf(a0.y + b0.y, 0.f);
    o0.z = fmaxf(a0.z + b0.z, 0.f); o0.w = fmaxf(a0.w + b0.w, 0.f);
    o1.x = fmaxf(a1.x + b1.x, 0.f); o1.y = fmaxf(a1.y + b1.y, 0.f);
    o1.z = fmaxf(a1.z + b1.z, 0.f); o1.w = fmaxf(a1.w + b1.w, 0.f);
    float4* op = (float4*)(out + (size_t)n * HW) + lane * 2;
    op[0] = o0; op[1] = o1;
}

// ---------------- host launcher ----------------
extern "C" void kernel_launch(void* const* d_in, const int* in_sizes, int n_in,
                              void* d_out, int out_size) {
    const float* x   = (const float*)d_in[0];
    const void*  ei  = d_in[1];
    const float* W1  = (const float*)d_in[2];
    const float* as1 = (const float*)d_in[3];
    const float* ad1 = (const float*)d_in[4];
    const float* b1  = (const float*)d_in[5];
    const float* W2  = (const float*)d_in[6];
    const float* as2 = (const float*)d_in[7];
    const float* ad2 = (const float*)d_in[8];
    const float* b2  = (const float*)d_in[9];
    const float* W3  = (const float*)d_in[10];
    const float* as3 = (const float*)d_in[11];
    const float* ad3 = (const float*)d_in[12];
    const float* b3  = (const float*)d_in[13];
    const float* Wm1 = (const float*)d_in[14];
    const float* bm1 = (const float*)d_in[15];
    const float* Wm2 = (const float*)d_in[16];
    const float* bm2 = (const float*)d_in[17];
    float* out = (float*)d_out;

    float *p_h, *p_feat, *p_srcl, *p_dstl, *p_denom, *p_coef;
    int *p_src2, *p_dst2, *p_srcs, *p_counts, *p_fill, *p_rowptr;
    cudaGetSymbolAddress((void**)&p_h, g_h);
    cudaGetSymbolAddress((void**)&p_feat, g_feat);
    cudaGetSymbolAddress((void**)&p_srcl, g_srcl);
    cudaGetSymbolAddress((void**)&p_dstl, g_dstl);
    cudaGetSymbolAddress((void**)&p_denom, g_denom);
    cudaGetSymbolAddress((void**)&p_coef, g_coef);
    cudaGetSymbolAddress((void**)&p_src2, g_src2);
    cudaGetSymbolAddress((void**)&p_dst2, g_dst2);
    cudaGetSymbolAddress((void**)&p_srcs, g_src_sorted);
    cudaGetSymbolAddress((void**)&p_counts, g_counts);
    cudaGetSymbolAddress((void**)&p_fill, g_fill);
    cudaGetSymbolAddress((void**)&p_rowptr, g_rowptr);

    // --- CSR build (once per call; reused by all 3 layers) ---
    k_detect<<<1, 32>>>(ei);
    k_zero_counts<<<(NN + 255) / 256, 256>>>(p_counts, NN);
    k_build_edges<<<(EE + 255) / 256, 256>>>(ei, p_src2, p_dst2, p_counts);
    k_scan<<<1, 1024>>>(p_counts, p_rowptr, p_fill);
    k_scatter<<<(EE + 255) / 256, 256>>>(p_src2, p_dst2, p_fill, p_srcs);

    const int warpsGrid = (NN * 32 + 255) / 256;     // warp-per-node kernels
    const int attnGrid  = (NN * 4 + 255) / 256;
    dim3 gemmGrid256(HW / BN, (NN + BM - 1) / BM);

    // --- GAT layer 1 (K = 128) ---
    k_sgemm<<<gemmGrid256, 256>>>(x, W1, p_h, NN, HW, IN_FEAT, nullptr, 0);
    k_logits<<<warpsGrid, 256>>>(p_h, as1, ad1, p_srcl, p_dstl);
    k_attn<<<attnGrid, 256>>>(p_srcl, p_dstl, p_rowptr, p_srcs, p_coef, p_denom);
    k_agg<<<warpsGrid, 256>>>(p_h, p_rowptr, p_srcs, p_coef, p_denom, b1, p_feat);

    // --- GAT layer 2 ---
    k_sgemm<<<gemmGrid256, 256>>>(p_feat, W2, p_h, NN, HW, HW, nullptr, 0);
    k_logits<<<warpsGrid, 256>>>(p_h, as2, ad2, p_srcl, p_dstl);
    k_attn<<<attnGrid, 256>>>(p_srcl, p_dstl, p_rowptr, p_srcs, p_coef, p_denom);
    k_agg<<<warpsGrid, 256>>>(p_h, p_rowptr, p_srcs, p_coef, p_denom, b2, p_feat);

    // --- GAT layer 3 ---
    k_sgemm<<<gemmGrid256, 256>>>(p_feat, W3, p_h, NN, HW, HW, nullptr, 0);
    k_logits<<<warpsGrid, 256>>>(p_h, as3, ad3, p_srcl, p_dstl);
    k_attn<<<attnGrid, 256>>>(p_srcl, p_dstl, p_rowptr, p_srcs, p_coef, p_denom);
    k_agg<<<warpsGrid, 256>>>(p_h, p_rowptr, p_srcs, p_coef, p_denom, b3, p_feat);

    // --- MLP head ---
    k_sgemm<<<gemmGrid256, 256>>>(p_feat, Wm1, p_h, NN, HW, HW, bm1, 1);
    dim3 gemmGrid40((OUTF + BN - 1) / BN, (NN + BM - 1) / BM);
    k_sgemm<<<gemmGrid40, 256>>>(p_h, Wm2, out, NN, OUTF, HW, bm2, 0);
}

// round 4
// speedup vs baseline: 1.3652x; 1.3652x over previous
#include <cuda_runtime.h>
#include <cuda_bf16.h>
#include <mma.h>
#include <cstdint>

using namespace nvcuda;

#define NN 50000
#define NE 800000
#define EE (NE + NN)   // edges + self loops = 850000
#define HW 256
#define IN_FEAT 128
#define OUTF 40

// ---------------- scratch (static device globals; no runtime allocation) ----
__device__ float g_h[NN * HW];      // transformed features  (x @ W)
__device__ float g_feat[NN * HW];   // layer output / next layer input
__device__ float g_srcl[NN * 4];
__device__ float g_dstl[NN * 4];
__device__ float g_denom[NN * 4];
__device__ float g_coef[EE * 4];    // per-edge (sorted order) exp values
__device__ int   g_src2[EE];
__device__ int   g_dst2[EE];
__device__ int   g_src_sorted[EE];
__device__ int   g_counts[NN];
__device__ int   g_fill[NN];
__device__ int   g_rowptr[NN + 1];
__device__ int   g_bsum[256];
__device__ int   g_is64;            // edge_index dtype flag

// ---------------- dtype detection: is edge_index int64 or int32? ----------
__global__ void k_detect(const void* __restrict__ ei) {
    if (threadIdx.x != 0 || blockIdx.x != 0) return;
    const long long* p64 = (const long long*)ei;
    bool ok64 = true;
    for (int i = 0; i < 512; i++) {
        long long v = p64[i];
        if (v < 0 || v >= (long long)NN) { ok64 = false; break; }
    }
    g_is64 = ok64 ? 1 : 0;
}

// ---------------- CSR build ----------------
__global__ void k_zero_counts(int* counts, int n) {
    int i = blockIdx.x * blockDim.x + threadIdx.x;
    if (i < n) counts[i] = 0;
}

__global__ void k_build_edges(const void* __restrict__ ei,
                              int* __restrict__ src2, int* __restrict__ dst2,
                              int* __restrict__ counts) {
    int e = blockIdx.x * blockDim.x + threadIdx.x;
    if (e >= EE) return;
    int s, d;
    if (e < NE) {
        if (g_is64) {
            const long long* p = (const long long*)ei;
            s = (int)p[e]; d = (int)p[NE + e];
        } else {
            const int* p = (const int*)ei;
            s = p[e]; d = p[NE + e];
        }
        s = min(max(s, 0), NN - 1);
        d = min(max(d, 0), NN - 1);
    } else {
        s = d = e - NE;          // self loop
    }
    src2[e] = s;
    dst2[e] = d;
    atomicAdd(&counts[d], 1);
}

// ---------------- hierarchical exclusive scan (counts -> rowptr, fill) -----
#define SCAN_B 256
#define SCAN_NB ((NN + SCAN_B - 1) / SCAN_B)   // 196

__global__ void k_blocksum(const int* __restrict__ counts, int* __restrict__ bsum) {
    __shared__ int s[SCAN_B];
    int i = blockIdx.x * SCAN_B + threadIdx.x;
    s[threadIdx.x] = (i < NN) ? counts[i] : 0;
    __syncthreads();
    for (int off = 128; off > 0; off >>= 1) {
        if (threadIdx.x < off) s[threadIdx.x] += s[threadIdx.x + off];
        __syncthreads();
    }
    if (threadIdx.x == 0) bsum[blockIdx.x] = s[0];
}

__global__ void k_scan_top(int* __restrict__ bsum) {   // 1 block, 256 threads
    __shared__ int s[SCAN_B];
    int v = (threadIdx.x < SCAN_NB) ? bsum[threadIdx.x] : 0;
    s[threadIdx.x] = v;
    __syncthreads();
    for (int off = 1; off < SCAN_B; off <<= 1) {
        int t = (threadIdx.x >= off) ? s[threadIdx.x - off] : 0;
        __syncthreads();
        s[threadIdx.x] += t;
        __syncthreads();
    }
    if (threadIdx.x < SCAN_NB) bsum[threadIdx.x] = s[threadIdx.x] - v;  // exclusive
}

__global__ void k_scan_final(const int* __restrict__ counts, const int* __restrict__ bsum,
                             int* __restrict__ rowptr, int* __restrict__ fill) {
    __shared__ int s[SCAN_B];
    int i = blockIdx.x * SCAN_B + threadIdx.x;
    int v = (i < NN) ? counts[i] : 0;
    s[threadIdx.x] = v;
    __syncthreads();
    for (int off = 1; off < SCAN_B; off <<= 1) {
        int t = (threadIdx.x >= off) ? s[threadIdx.x - off] : 0;
        __syncthreads();
        s[threadIdx.x] += t;
        __syncthreads();
    }
    int excl = bsum[blockIdx.x] + s[threadIdx.x] - v;
    if (i < NN) { rowptr[i] = excl; fill[i] = excl; }
    if (i == NN - 1) rowptr[NN] = excl + v;
}

__global__ void k_scatter(const int* __restrict__ src2, const int* __restrict__ dst2,
                          int* __restrict__ fill, int* __restrict__ src_sorted) {
    int e = blockIdx.x * blockDim.x + threadIdx.x;
    if (e >= EE) return;
    int d = dst2[e];
    int p = atomicAdd(&fill[d], 1);
    src_sorted[p] = src2[e];
}

// ---------------- tf32 tensor-core GEMM: C[M,N] = A[M,K] @ B[K,N] ----------
// block 256 threads = 8 warps (4 along M x 2 along N); warp owns 32x32;
// block tile 128x64; K step 16.
#define GBM 128
#define GBN 64
#define GBK 16

__global__ __launch_bounds__(256) void k_gemm_tf32(
    const float* __restrict__ A, const float* __restrict__ B,
    float* __restrict__ C, int M, int N, int K,
    const float* __restrict__ bias, int do_relu)
{
    __shared__ float As[GBM][GBK + 4];   // 128 x 20
    __shared__ float Bs[GBK][GBN + 4];   // 16 x 68
    __shared__ float Cs[GBM][GBN];       // 128 x 64

    int tid = threadIdx.x;
    int warp = tid >> 5;
    int wm = warp >> 1;      // 0..3
    int wn = warp & 1;       // 0..1
    int row0 = blockIdx.y * GBM;
    int col0 = blockIdx.x * GBN;

    wmma::fragment<wmma::accumulator, 16, 16, 8, float> acc[2][2];
#pragma unroll
    for (int i = 0; i < 2; i++)
#pragma unroll
        for (int j = 0; j < 2; j++) wmma::fill_fragment(acc[i][j], 0.0f);

    for (int k0 = 0; k0 < K; k0 += GBK) {
        // A tile: 128x16 floats = 512 float4; 2 per thread
#pragma unroll
        for (int t = 0; t < 2; t++) {
            int idx = tid + t * 256;
            int r = idx >> 2;
            int c4 = (idx & 3) * 4;
            float4 v = make_float4(0.f, 0.f, 0.f, 0.f);
            if (row0 + r < M)
                v = *(const float4*)(A + (size_t)(row0 + r) * K + k0 + c4);
            As[r][c4 + 0] = wmma::__float_to_tf32(v.x);
            As[r][c4 + 1] = wmma::__float_to_tf32(v.y);
            As[r][c4 + 2] = wmma::__float_to_tf32(v.z);
            As[r][c4 + 3] = wmma::__float_to_tf32(v.w);
        }
        // B tile: 16x64; 4 scalars per thread (guards for N=40 tail)
        {
            int r = tid >> 4;
            int c0 = (tid & 15) * 4;
#pragma unroll
            for (int j = 0; j < 4; j++) {
                int c = c0 + j;
                float v = 0.f;
                if (col0 + c < N) v = B[(size_t)(k0 + r) * N + col0 + c];
                Bs[r][c] = wmma::__float_to_tf32(v);
            }
        }
        __syncthreads();

#pragma unroll
        for (int kk = 0; kk < GBK; kk += 8) {
            wmma::fragment<wmma::matrix_a, 16, 16, 8, wmma::precision::tf32, wmma::row_major> a[2];
            wmma::fragment<wmma::matrix_b, 16, 16, 8, wmma::precision::tf32, wmma::row_major> b[2];
            wmma::load_matrix_sync(a[0], &As[wm * 32 +  0][kk], GBK + 4);
            wmma::load_matrix_sync(a[1], &As[wm * 32 + 16][kk], GBK + 4);
            wmma::load_matrix_sync(b[0], &Bs[kk][wn * 32 +  0], GBN + 4);
            wmma::load_matrix_sync(b[1], &Bs[kk][wn * 32 + 16], GBN + 4);
#pragma unroll
            for (int i = 0; i < 2; i++)
#pragma unroll
                for (int j = 0; j < 2; j++)
                    wmma::mma_sync(acc[i][j], a[i], b[j], acc[i][j]);
        }
        __syncthreads();
    }

    // epilogue via smem (bias / relu / boundary guards)
#pragma unroll
    for (int i = 0; i < 2; i++)
#pragma unroll
        for (int j = 0; j < 2; j++)
            wmma::store_matrix_sync(&Cs[wm * 32 + i * 16][wn * 32 + j * 16],
                                    acc[i][j], GBN, wmma::mem_row_major);
    __syncthreads();

#pragma unroll
    for (int it = 0; it < 8; it++) {
        int idx = tid + it * 256;        // 0..2047
        int r = idx >> 4;                // 0..127
        int c4 = (idx & 15) * 4;
        int gr = row0 + r;
        if (gr >= M) continue;
        float4 v = *(const float4*)&Cs[r][c4];
        int gc = col0 + c4;
        float* vv = &v.x;
        if (bias) {
#pragma unroll
            for (int j = 0; j < 4; j++)
                if (gc + j < N) vv[j] += bias[gc + j];
        }
        if (do_relu) {
#pragma unroll
            for (int j = 0; j < 4; j++) vv[j] = fmaxf(vv[j], 0.f);
        }
        if (gc + 4 <= N) {
            *(float4*)(C + (size_t)gr * N + gc) = v;
        } else {
#pragma unroll
            for (int j = 0; j < 4; j++)
                if (gc + j < N) C[(size_t)gr * N + gc + j] = vv[j];
        }
    }
}

// ---------------- per-node attention logits: warp per node ----------------
__global__ void k_logits(const float* __restrict__ h, const float* __restrict__ a_s,
                         const float* __restrict__ a_d,
                         float* __restrict__ srcl, float* __restrict__ dstl) {
    int warp = (blockIdx.x * blockDim.x + threadIdx.x) >> 5;
    int lane = threadIdx.x & 31;
    if (warp >= NN) return;
    int n = warp;
    const float4* hp = (const float4*)(h + (size_t)n * HW) + lane * 2;
    float4 v0 = hp[0], v1 = hp[1];
    int head = lane >> 3, sub = lane & 7;
    const float4* ap = (const float4*)(a_s + head * 64 + sub * 8);
    const float4* dp = (const float4*)(a_d + head * 64 + sub * 8);
    float4 s0 = ap[0], s1 = ap[1];
    float4 d0 = dp[0], d1 = dp[1];
    float ps = v0.x * s0.x + v0.y * s0.y + v0.z * s0.z + v0.w * s0.w
             + v1.x * s1.x + v1.y * s1.y + v1.z * s1.z + v1.w * s1.w;
    float pd = v0.x * d0.x + v0.y * d0.y + v0.z * d0.z + v0.w * d0.w
             + v1.x * d1.x + v1.y * d1.y + v1.z * d1.z + v1.w * d1.w;
#pragma unroll
    for (int off = 4; off >= 1; off >>= 1) {
        ps += __shfl_down_sync(0xffffffffu, ps, off, 8);
        pd += __shfl_down_sync(0xffffffffu, pd, off, 8);
    }
    if (sub == 0) {
        srcl[n * 4 + head] = ps;
        dstl[n * 4 + head] = pd;
    }
}

// ---------------- segment softmax: one thread per (node, head) ----------------
__global__ void k_attn(const float* __restrict__ srcl, const float* __restrict__ dstl,
                       const int* __restrict__ rowptr, const int* __restrict__ src_sorted,
                       float* __restrict__ coef, float* __restrict__ denom) {
    int t = blockIdx.x * blockDim.x + threadIdx.x;
    if (t >= NN * 4) return;
    int n = t >> 2, hd = t & 3;
    float dl = dstl[t];
    int b = rowptr[n], e = rowptr[n + 1];
    float mx = -1e30f;
    for (int i = b; i < e; i++) {
        int s = src_sorted[i];
        float a = srcl[s * 4 + hd] + dl;
        a = a > 0.f ? a : 0.2f * a;       // leaky_relu(0.2)
        coef[i * 4 + hd] = a;
        mx = fmaxf(mx, a);
    }
    float sum = 0.f;
    for (int i = b; i < e; i++) {
        float ev = __expf(coef[i * 4 + hd] - mx);
        coef[i * 4 + hd] = ev;
        sum += ev;
    }
    denom[t] = sum;
}

// ---------------- aggregation: warp per destination node, no atomics -------
__global__ void k_agg(const float* __restrict__ h, const int* __restrict__ rowptr,
                      const int* __restrict__ src_sorted, const float* __restrict__ coef,
                      const float* __restrict__ denom, const float* __restrict__ bias,
                      float* __restrict__ out) {
    int warp = (blockIdx.x * blockDim.x + threadIdx.x) >> 5;
    int lane = threadIdx.x & 31;
    if (warp >= NN) return;
    int n = warp;
    int head = lane >> 3;
    float rinv = 1.0f / denom[n * 4 + head];
    int b = rowptr[n], e = rowptr[n + 1];
    float4 a0 = make_float4(0.f, 0.f, 0.f, 0.f);
    float4 a1 = make_float4(0.f, 0.f, 0.f, 0.f);
    for (int i = b; i < e; i++) {
        int s = src_sorted[i];
        float4 cq = ((const float4*)coef)[i];
        float c = (head == 0) ? cq.x : (head == 1) ? cq.y : (head == 2) ? cq.z : cq.w;
        c *= rinv;
        const float4* hp = (const float4*)(h + (size_t)s * HW) + lane * 2;
        float4 v0 = hp[0], v1 = hp[1];
        a0.x += v0.x * c; a0.y += v0.y * c; a0.z += v0.z * c; a0.w += v0.w * c;
        a1.x += v1.x * c; a1.y += v1.y * c; a1.z += v1.z * c; a1.w += v1.w * c;
    }
    const float4* bp = (const float4*)bias + lane * 2;
    float4 b0 = bp[0], b1 = bp[1];
    float4 o0, o1;
    o0.x = fmaxf(a0.x + b0.x, 0.f); o0.y = fmaxf(a0.y + b0.y, 0.f);
    o0.z = fmaxf(a0.z + b0.z, 0.f); o0.w = fmaxf(a0.w + b0.w, 0.f);
    o1.x = fmaxf(a1.x + b1.x, 0.f); o1.y = fmaxf(a1.y + b1.y, 0.f);
    o1.z = fmaxf(a1.z + b1.z, 0.f); o1.w = fmaxf(a1.w + b1.w, 0.f);
    float4* op = (float4*)(out + (size_t)n * HW) + lane * 2;
    op[0] = o0; op[1] = o1;
}

// ---------------- host launcher ----------------
extern "C" void kernel_launch(void* const* d_in, const int* in_sizes, int n_in,
                              void* d_out, int out_size) {
    const float* x   = (const float*)d_in[0];
    const void*  ei  = d_in[1];
    const float* W1  = (const float*)d_in[2];
    const float* as1 = (const float*)d_in[3];
    const float* ad1 = (const float*)d_in[4];
    const float* b1  = (const float*)d_in[5];
    const float* W2  = (const float*)d_in[6];
    const float* as2 = (const float*)d_in[7];
    const float* ad2 = (const float*)d_in[8];
    const float* b2  = (const float*)d_in[9];
    const float* W3  = (const float*)d_in[10];
    const float* as3 = (const float*)d_in[11];
    const float* ad3 = (const float*)d_in[12];
    const float* b3  = (const float*)d_in[13];
    const float* Wm1 = (const float*)d_in[14];
    const float* bm1 = (const float*)d_in[15];
    const float* Wm2 = (const float*)d_in[16];
    const float* bm2 = (const float*)d_in[17];
    float* out = (float*)d_out;

    float *p_h, *p_feat, *p_srcl, *p_dstl, *p_denom, *p_coef;
    int *p_src2, *p_dst2, *p_srcs, *p_counts, *p_fill, *p_rowptr, *p_bsum;
    cudaGetSymbolAddress((void**)&p_h, g_h);
    cudaGetSymbolAddress((void**)&p_feat, g_feat);
    cudaGetSymbolAddress((void**)&p_srcl, g_srcl);
    cudaGetSymbolAddress((void**)&p_dstl, g_dstl);
    cudaGetSymbolAddress((void**)&p_denom, g_denom);
    cudaGetSymbolAddress((void**)&p_coef, g_coef);
    cudaGetSymbolAddress((void**)&p_src2, g_src2);
    cudaGetSymbolAddress((void**)&p_dst2, g_dst2);
    cudaGetSymbolAddress((void**)&p_srcs, g_src_sorted);
    cudaGetSymbolAddress((void**)&p_counts, g_counts);
    cudaGetSymbolAddress((void**)&p_fill, g_fill);
    cudaGetSymbolAddress((void**)&p_rowptr, g_rowptr);
    cudaGetSymbolAddress((void**)&p_bsum, g_bsum);

    // --- CSR build (once per call; reused by all 3 layers) ---
    k_detect<<<1, 32>>>(ei);
    k_zero_counts<<<(NN + 255) / 256, 256>>>(p_counts, NN);
    k_build_edges<<<(EE + 255) / 256, 256>>>(ei, p_src2, p_dst2, p_counts);
    k_blocksum<<<SCAN_NB, SCAN_B>>>(p_counts, p_bsum);
    k_scan_top<<<1, SCAN_B>>>(p_bsum);
    k_scan_final<<<SCAN_NB, SCAN_B>>>(p_counts, p_bsum, p_rowptr, p_fill);
    k_scatter<<<(EE + 255) / 256, 256>>>(p_src2, p_dst2, p_fill, p_srcs);

    const int warpsGrid = (NN * 32 + 255) / 256;
    const int attnGrid  = (NN * 4 + 255) / 256;
    dim3 gGrid(HW / GBN, (NN + GBM - 1) / GBM);          // (4, 391)
    dim3 gGridOut((OUTF + GBN - 1) / GBN, (NN + GBM - 1) / GBM);  // (1, 391)

    // --- GAT layer 1 (K = 128) ---
    k_gemm_tf32<<<gGrid, 256>>>(x, W1, p_h, NN, HW, IN_FEAT, nullptr, 0);
    k_logits<<<warpsGrid, 256>>>(p_h, as1, ad1, p_srcl, p_dstl);
    k_attn<<<attnGrid, 256>>>(p_srcl, p_dstl, p_rowptr, p_srcs, p_coef, p_denom);
    k_agg<<<warpsGrid, 256>>>(p_h, p_rowptr, p_srcs, p_coef, p_denom, b1, p_feat);

    // --- GAT layer 2 ---
    k_gemm_tf32<<<gGrid, 256>>>(p_feat, W2, p_h, NN, HW, HW, nullptr, 0);
    k_logits<<<warpsGrid, 256>>>(p_h, as2, ad2, p_srcl, p_dstl);
    k_attn<<<attnGrid, 256>>>(p_srcl, p_dstl, p_rowptr, p_srcs, p_coef, p_denom);
    k_agg<<<warpsGrid, 256>>>(p_h, p_rowptr, p_srcs, p_coef, p_denom, b2, p_feat);

    // --- GAT layer 3 ---
    k_gemm_tf32<<<gGrid, 256>>>(p_feat, W3, p_h, NN, HW, HW, nullptr, 0);
    k_logits<<<warpsGrid, 256>>>(p_h, as3, ad3, p_srcl, p_dstl);
    k_attn<<<attnGrid, 256>>>(p_srcl, p_dstl, p_rowptr, p_srcs, p_coef, p_denom);
    k_agg<<<warpsGrid, 256>>>(p_h, p_rowptr, p_srcs, p_coef, p_denom, b3, p_feat);

    // --- MLP head ---
    k_gemm_tf32<<<gGrid, 256>>>(p_feat, Wm1, p_h, NN, HW, HW, bm1, 1);
    k_gemm_tf32<<<gGridOut, 256>>>(p_h, Wm2, out, NN, OUTF, HW, bm2, 0);
}